// round 16
// baseline (speedup 1.0000x reference)
#include <cuda_runtime.h>
#include <cuda_fp16.h>
#include <math.h>
#include <stdint.h>

// Problem constants
#define BATCH 2
#define TSEQ  2048
#define CDIM  1024
#define NHEAD 16
#define HDIM  64
#define MROWS (BATCH * TSEQ)   // 4096

// ---------------------------------------------------------------------------
// Scratch (allocation-free: __device__ globals)
// ---------------------------------------------------------------------------
__device__ __align__(16) __half g_xh[MROWS * CDIM];
__device__ __align__(16) __half g_qh[MROWS * CDIM];
__device__ __align__(16) __half g_kh[MROWS * CDIM];
__device__ __align__(16) __half g_vh[MROWS * CDIM];
__device__ __align__(16) __half g_yh[MROWS * CDIM];
__device__ __align__(16) __half g_wqh[CDIM * CDIM];
__device__ __align__(16) __half g_wkh[CDIM * CDIM];
__device__ __align__(16) __half g_wvh[CDIM * CDIM];
__device__ __align__(16) __half g_woh[CDIM * CDIM];

// ---------------------------------------------------------------------------
// PTX helpers (baseline PTX, valid for compute_103)
// ---------------------------------------------------------------------------
__device__ __forceinline__ void mma16816(float* c, const uint32_t* a,
                                         const uint32_t* b) {
    asm volatile(
        "mma.sync.aligned.m16n8k16.row.col.f32.f16.f16.f32 "
        "{%0,%1,%2,%3}, {%4,%5,%6,%7}, {%8,%9}, {%0,%1,%2,%3};"
        : "+f"(c[0]), "+f"(c[1]), "+f"(c[2]), "+f"(c[3])
        : "r"(a[0]), "r"(a[1]), "r"(a[2]), "r"(a[3]), "r"(b[0]), "r"(b[1]));
}

__device__ __forceinline__ void ldm_x4(uint32_t* r, uint32_t saddr) {
    asm volatile(
        "ldmatrix.sync.aligned.m8n8.x4.shared.b16 {%0,%1,%2,%3}, [%4];"
        : "=r"(r[0]), "=r"(r[1]), "=r"(r[2]), "=r"(r[3]) : "r"(saddr));
}

__device__ __forceinline__ void ldm_x4_trans(uint32_t* r, uint32_t saddr) {
    asm volatile(
        "ldmatrix.sync.aligned.m8n8.x4.trans.shared.b16 {%0,%1,%2,%3}, [%4];"
        : "=r"(r[0]), "=r"(r[1]), "=r"(r[2]), "=r"(r[3]) : "r"(saddr));
}

__device__ __forceinline__ uint32_t smem_u32(const void* p) {
    uint32_t a;
    asm("{ .reg .u64 t; cvta.to.shared.u64 t, %1; cvt.u32.u64 %0, t; }"
        : "=r"(a) : "l"(p));
    return a;
}

__device__ __forceinline__ void cpa16(uint32_t s, const void* g) {
    asm volatile("cp.async.cg.shared.global [%0], [%1], 16;"
                 :: "r"(s), "l"(g));
}
__device__ __forceinline__ void cpa_commit() {
    asm volatile("cp.async.commit_group;");
}
template<int N> __device__ __forceinline__ void cpa_wait() {
    asm volatile("cp.async.wait_group %0;" :: "n"(N));
}

__device__ __forceinline__ uint32_t packh(__half a, __half b) {
    __half2 t = __halves2half2(a, b);
    return *(uint32_t*)&t;
}

__device__ __forceinline__ uint32_t cvt2h(float a, float b) {
    return packh(__float2half_rn(a), __float2half_rn(b));
}

// 2^x on packed fp16 pair (approx; baseline PTX sm_75+)
__device__ __forceinline__ uint32_t ex2h2(uint32_t x) {
    uint32_t r;
    asm("ex2.approx.f16x2 %0, %1;" : "=r"(r) : "r"(x));
    return r;
}

// ---------------------------------------------------------------------------
// Convert kernel: 8 segments (4 weights + 4 quarters of x), fp32 -> fp16
// ---------------------------------------------------------------------------
struct CvtAll {
    const float* in[8];
    __half* out[8];
};

__global__ void __launch_bounds__(256)
cvt8_kernel(CvtAll cb, int n4)
{
    int i = blockIdx.x * blockDim.x + threadIdx.x;
    if (i >= n4) return;
    const float* in = cb.in[blockIdx.y];
    __half* out = cb.out[blockIdx.y];
    float4 v = ((const float4*)in)[i];
    ((uint32_t*)out)[2 * i]     = cvt2h(v.x, v.y);
    ((uint32_t*)out)[2 * i + 1] = cvt2h(v.z, v.w);
}

// ---------------------------------------------------------------------------
// HMMA GEMM body: C = A[M,K] @ B[N,K]^T + bias. fp16 (1 MMA per frag).
// CTA tile 128x128, K-chunk 64, triple-buffered cp.async (wait_group 1),
// register-pipelined ldmatrix fragments, ONE barrier per chunk.
// OUT: 0 = fp32 C; 2 = fp16 Ch.
// ---------------------------------------------------------------------------
#define SSTR  36                     // u32 per smem row (64 fp16 + pad)
#define GARRB (128 * SSTR * 4)       // bytes per array (18432)
#define GBUFB (2 * GARRB)            // bytes per buffer
#define GEMM_SMEM (3 * GBUFB)        // 110592

template<int OUT>
__device__ __forceinline__ void
gemm_body(uint32_t* sg,
          const __half* __restrict__ Ah, const __half* __restrict__ Bh,
          const float* __restrict__ bias, float* __restrict__ C,
          __half* __restrict__ Ch,
          int M, int N, int K)
{
    const uint32_t sbase = smem_u32(sg);

    const int tid  = threadIdx.x;
    const int lane = tid & 31;
    const int warp = tid >> 5;
    const int wm   = (warp >> 1) * 32;
    const int wn   = (warp & 1) * 64;
    const int m0   = blockIdx.y * 128;
    const int n0   = blockIdx.x * 128;

    // cp.async: base addresses + derived per-slot offsets (register-lean)
    const int   lrow = tid >> 3;
    const int   lc8  = tid & 7;
    const uint32_t sO = (uint32_t)(lrow * SSTR + lc8 * 4) * 4;   // slot 0 smem off
    const size_t  gA0 = (size_t)(m0 + lrow) * K + lc8 * 8;
    const size_t  gB0 = (size_t)(n0 + lrow) * K + lc8 * 8;
    const size_t  tstr = (size_t)32 * K;                         // +32 rows
    const uint32_t sstr = (uint32_t)(32 * SSTR) * 4;

    const int arow  = (lane & 7) + ((lane >> 3) & 1) * 8;
    const int acol  = (lane >> 4) * 4;
    const int brow  = (lane & 7) + (lane >> 4) * 8;
    const int bcol4 = ((lane >> 3) & 1) * 4;

    uint32_t aoff[2], boff[4];
    #pragma unroll
    for (int mt = 0; mt < 2; mt++)
        aoff[mt] = (uint32_t)((wm + mt * 16 + arow) * SSTR + acol) * 4;
    #pragma unroll
    for (int np = 0; np < 4; np++)
        boff[np] = (uint32_t)((wn + np * 16 + brow) * SSTR + bcol4) * 4;

    const int fr = lane >> 2;
    const int fc = lane & 3;

    float acc[2][8][4];
    #pragma unroll
    for (int mt = 0; mt < 2; mt++)
        #pragma unroll
        for (int nt = 0; nt < 8; nt++)
            #pragma unroll
            for (int j = 0; j < 4; j++) acc[mt][nt][j] = 0.f;

    const int nchunks = K / 64;   // 16

    // prefetch chunks 0,1 -> buffers 0,1
    #pragma unroll
    for (int pc = 0; pc < 2; pc++) {
        const uint32_t bb = sbase + pc * GBUFB;
        const int ko = pc * 64;
        #pragma unroll
        for (int t = 0; t < 4; t++) {
            cpa16(bb + 0 * GARRB + sO + t * sstr, Ah + gA0 + t * tstr + ko);
            cpa16(bb + 1 * GARRB + sO + t * sstr, Bh + gB0 + t * tstr + ko);
        }
        cpa_commit();
    }

    int buf = 0;
    for (int kc = 0; kc < nchunks; kc++) {
        cpa_wait<1>();
        __syncthreads();

        if (kc + 2 < nchunks) {
            int pb = buf + 2; if (pb >= 3) pb -= 3;
            const uint32_t bb = sbase + pb * GBUFB;
            const int ko = (kc + 2) * 64;
            #pragma unroll
            for (int t = 0; t < 4; t++) {
                cpa16(bb + 0 * GARRB + sO + t * sstr, Ah + gA0 + t * tstr + ko);
                cpa16(bb + 1 * GARRB + sO + t * sstr, Bh + gB0 + t * tstr + ko);
            }
            cpa_commit();
        } else {
            cpa_commit();
        }

        const uint32_t cb  = sbase + buf * GBUFB;
        const uint32_t aAh = cb, aBh = cb + GARRB;

        // register-pipelined fragments (parity double buffers)
        uint32_t ab[2][2][4], bb2[2][4];
        ldm_x4(ab[0][0], aAh + aoff[0]);
        ldm_x4(ab[0][1], aAh + aoff[1]);
        ldm_x4(bb2[0], aBh + boff[0]);

        #pragma unroll
        for (int ks = 0; ks < 4; ks++) {
            const int kp = ks & 1;
            if (ks < 3) {
                ldm_x4(ab[kp ^ 1][0], aAh + aoff[0] + (uint32_t)(ks + 1) * 32);
                ldm_x4(ab[kp ^ 1][1], aAh + aoff[1] + (uint32_t)(ks + 1) * 32);
            }
            #pragma unroll
            for (int np = 0; np < 4; np++) {
                const int i  = ks * 4 + np;
                const int bp = i & 1;
                if (i < 15) {
                    const int ni = i + 1;
                    ldm_x4(bb2[bp ^ 1],
                           aBh + boff[ni & 3] + (uint32_t)(ni >> 2) * 32);
                }
                #pragma unroll
                for (int hf = 0; hf < 2; hf++) {
                    const int nt = np * 2 + hf;
                    mma16816(acc[0][nt], ab[kp][0], &bb2[bp][hf * 2]);
                    mma16816(acc[1][nt], ab[kp][1], &bb2[bp][hf * 2]);
                }
            }
        }
        buf++; if (buf == 3) buf = 0;
    }

    #pragma unroll
    for (int mt = 0; mt < 2; mt++) {
        #pragma unroll
        for (int nt = 0; nt < 8; nt++) {
            int row = m0 + wm + mt * 16 + fr;
            int col = n0 + wn + nt * 8 + fc * 2;
            float b0 = __ldg(&bias[col]);
            float b1 = __ldg(&bias[col + 1]);
            float c0 = acc[mt][nt][0] + b0, c1 = acc[mt][nt][1] + b1;
            float c2 = acc[mt][nt][2] + b0, c3 = acc[mt][nt][3] + b1;
            if (OUT == 2) {
                *(uint32_t*)&Ch[(size_t)row * N + col]       = cvt2h(c0, c1);
                *(uint32_t*)&Ch[(size_t)(row + 8) * N + col] = cvt2h(c2, c3);
            } else {
                *(float2*)&C[(size_t)row * N + col]       = make_float2(c0, c1);
                *(float2*)&C[(size_t)(row + 8) * N + col] = make_float2(c2, c3);
            }
        }
    }
}

struct GemmBatch {
    const __half* Bh[3];
    const float* bias[3];
    __half* Ch[3];
};

__global__ void __launch_bounds__(256, 2)
gemm_qkv(GemmBatch gb, const __half* __restrict__ Ah)
{
    extern __shared__ uint32_t sg[];
    const int z = blockIdx.z;
    gemm_body<2>(sg, Ah, gb.Bh[z], gb.bias[z], nullptr, gb.Ch[z],
                 MROWS, CDIM, CDIM);
}

__global__ void __launch_bounds__(256, 2)
gemm_o(const __half* __restrict__ Ah, const __half* __restrict__ Bh,
       const float* __restrict__ bias, float* __restrict__ C)
{
    extern __shared__ uint32_t sg[];
    gemm_body<0>(sg, Ah, Bh, bias, C, nullptr, MROWS, CDIM, CDIM);
}

// ---------------------------------------------------------------------------
// HMMA flash attention (causal). fp16 operands, fp32 softmax stats.
// Base-2 softmax via ex2.approx.f16x2; row sums via ones-MMA; Q hoisted;
// register-pipelined K/V fragments; triple-buffered cp.async KV.
// 128-row q tile/CTA, Bc=64, longest-qt-first, ONE barrier per kv tile.
// ---------------------------------------------------------------------------
#define QSTR 36
#define QARR (128 * QSTR)              // 4608 u32
#define KARR (64 * QSTR)               // 2304 u32
#define KBUF (2 * KARR)                // u32 per kv buffer (kh + vh)
#define ATTN_SMEM ((QARR + 3 * KBUF) * 4)   // 73728 B
#define ONE2 0x3C003C00u               // fp16x2 {1.0, 1.0}

__global__ void __launch_bounds__(256, 2)
attn_mma(const __half* __restrict__ Qh,
         const __half* __restrict__ Kh, const __half* __restrict__ Vh,
         __half* __restrict__ Yh)
{
    extern __shared__ uint32_t s32[];
    const uint32_t sbase = smem_u32(s32);
    const uint32_t aQh = sbase;

    const int qt = gridDim.x - 1 - blockIdx.x;   // longest-first
    const int bh = blockIdx.y;
    const int b  = bh >> 4;
    const int h  = bh & 15;
    const size_t headoff = (size_t)b * TSEQ * CDIM + (size_t)h * HDIM;

    const int tid  = threadIdx.x;
    const int lane = tid & 31;
    const int warp = tid >> 5;
    const int fr   = lane >> 2;
    const int fc   = lane & 3;
    const int wm   = warp * 16;

    const int arow  = (lane & 7) + ((lane >> 3) & 1) * 8;
    const int acol  = (lane >> 4) * 4;
    const int brow  = (lane & 7) + (lane >> 4) * 8;
    const int bcol4 = ((lane >> 3) & 1) * 4;
    const uint32_t qoff = (uint32_t)((wm + arow) * QSTR + acol) * 4;
    uint32_t koff[4], voff[4];
    #pragma unroll
    for (int np = 0; np < 4; np++) {
        koff[np] = (uint32_t)((np * 16 + brow) * QSTR + bcol4) * 4;
        voff[np] = (uint32_t)(arow * QSTR + (np * 2 + (lane >> 4)) * 4) * 4;
    }

    // cp.async slot bases
    const int   lrow = tid >> 3;
    const int   lc8  = tid & 7;
    const uint32_t kvsO = (uint32_t)(lrow * QSTR + lc8 * 4) * 4;
    const size_t  kvg0  = headoff + (size_t)lrow * CDIM + lc8 * 8;
    const size_t  tstr  = (size_t)32 * CDIM;
    const uint32_t sstr = (uint32_t)(32 * QSTR) * 4;
    const uint32_t kvbase = sbase + QARR * 4;

    const int ktmax = 2 * qt + 1;

    // group 0: Q tile + kv tile 0
    #pragma unroll
    for (int t = 0; t < 4; t++)
        cpa16(aQh + kvsO + t * sstr,
              Qh + kvg0 + (size_t)(qt * 128) * CDIM + t * tstr);
    #pragma unroll
    for (int t = 0; t < 2; t++) {
        cpa16(kvbase + 0 * KARR * 4 + kvsO + t * sstr, Kh + kvg0 + t * tstr);
        cpa16(kvbase + 1 * KARR * 4 + kvsO + t * sstr, Vh + kvg0 + t * tstr);
    }
    cpa_commit();

    // group 1: kv tile 1
    {
        const uint32_t bb = kvbase + KBUF * 4;
        const size_t go = (size_t)64 * CDIM;
        #pragma unroll
        for (int t = 0; t < 2; t++) {
            cpa16(bb + 0 * KARR * 4 + kvsO + t * sstr, Kh + kvg0 + go + t * tstr);
            cpa16(bb + 1 * KARR * 4 + kvsO + t * sstr, Vh + kvg0 + go + t * tstr);
        }
        cpa_commit();
    }

    const float C2 = 0.125f * 1.4426950408889634f;   // scale * log2(e)
    float o[8][4];
    #pragma unroll
    for (int nt = 0; nt < 8; nt++)
        #pragma unroll
        for (int j = 0; j < 4; j++) o[nt][j] = 0.f;
    float mA = -INFINITY, mB = -INFINITY, lA = 0.f, lB = 0.f;

    const int rowAg = qt * 128 + wm + fr;
    const int rowBg = rowAg + 8;

    const uint32_t ones[2] = {ONE2, ONE2};
    uint32_t qfrag[4][4];

    int buf = 0;
    for (int kt = 0; kt <= ktmax; kt++) {
        cpa_wait<1>();
        __syncthreads();

        if (kt == 0) {
            #pragma unroll
            for (int ks = 0; ks < 4; ks++)
                ldm_x4(qfrag[ks], aQh + qoff + (uint32_t)(ks * 8) * 4);
        }

        if (kt + 2 <= ktmax) {
            int pb = buf + 2; if (pb >= 3) pb -= 3;
            const uint32_t bb = kvbase + pb * KBUF * 4;
            const size_t go = (size_t)(kt + 2) * 64 * CDIM;
            #pragma unroll
            for (int t = 0; t < 2; t++) {
                cpa16(bb + 0 * KARR * 4 + kvsO + t * sstr, Kh + kvg0 + go + t * tstr);
                cpa16(bb + 1 * KARR * 4 + kvsO + t * sstr, Vh + kvg0 + go + t * tstr);
            }
            cpa_commit();
        } else {
            cpa_commit();
        }

        const uint32_t cb  = kvbase + buf * KBUF * 4;
        const uint32_t aKh = cb, aVh = cb + KARR * 4;

        // ---- S = Q K^T (register-pipelined K fragments) ----
        float sacc[8][4];
        #pragma unroll
        for (int nt = 0; nt < 8; nt++)
            #pragma unroll
            for (int j = 0; j < 4; j++) sacc[nt][j] = 0.f;

        {
            uint32_t kb[2][4];
            ldm_x4(kb[0], aKh + koff[0]);
            #pragma unroll
            for (int ks = 0; ks < 4; ks++) {
                #pragma unroll
                for (int np = 0; np < 4; np++) {
                    const int i  = ks * 4 + np;
                    const int bp = i & 1;
                    if (i < 15) {
                        const int ni = i + 1;
                        ldm_x4(kb[bp ^ 1],
                               aKh + koff[ni & 3] + (uint32_t)(ni >> 2) * 32);
                    }
                    mma16816(sacc[np * 2],     qfrag[ks], &kb[bp][0]);
                    mma16816(sacc[np * 2 + 1], qfrag[ks], &kb[bp][2]);
                }
            }
        }

        // scale (base-2) + causal mask
        const bool diag = (kt >= 2 * qt);
        #pragma unroll
        for (int nt = 0; nt < 8; nt++) {
            #pragma unroll
            for (int j = 0; j < 4; j++) sacc[nt][j] *= C2;
            if (diag) {
                int col0 = kt * 64 + nt * 8 + 2 * fc;
                if (col0     > rowAg) sacc[nt][0] = -INFINITY;
                if (col0 + 1 > rowAg) sacc[nt][1] = -INFINITY;
                if (col0     > rowBg) sacc[nt][2] = -INFINITY;
                if (col0 + 1 > rowBg) sacc[nt][3] = -INFINITY;
            }
        }

        // row max (base-2 domain)
        float mxA = -INFINITY, mxB = -INFINITY;
        #pragma unroll
        for (int nt = 0; nt < 8; nt++) {
            mxA = fmaxf(mxA, fmaxf(sacc[nt][0], sacc[nt][1]));
            mxB = fmaxf(mxB, fmaxf(sacc[nt][2], sacc[nt][3]));
        }
        mxA = fmaxf(mxA, __shfl_xor_sync(0xffffffffu, mxA, 1));
        mxA = fmaxf(mxA, __shfl_xor_sync(0xffffffffu, mxA, 2));
        mxB = fmaxf(mxB, __shfl_xor_sync(0xffffffffu, mxB, 1));
        mxB = fmaxf(mxB, __shfl_xor_sync(0xffffffffu, mxB, 2));

        float mnA = fmaxf(mA, mxA), mnB = fmaxf(mB, mxB);
        float aA = exp2f(mA - mnA), aB = exp2f(mB - mnB);
        mA = mnA; mB = mnB;

        // P = 2^(t - m) as fp16 PV A-fragments
        uint32_t pfrag[4][4];
        #pragma unroll
        for (int ks = 0; ks < 4; ks++) {
            pfrag[ks][0] = ex2h2(cvt2h(sacc[2*ks][0]   - mnA, sacc[2*ks][1]   - mnA));
            pfrag[ks][1] = ex2h2(cvt2h(sacc[2*ks][2]   - mnB, sacc[2*ks][3]   - mnB));
            pfrag[ks][2] = ex2h2(cvt2h(sacc[2*ks+1][0] - mnA, sacc[2*ks+1][1] - mnA));
            pfrag[ks][3] = ex2h2(cvt2h(sacc[2*ks+1][2] - mnB, sacc[2*ks+1][3] - mnB));
        }

        // row sums via ones-MMA
        float lacc[4] = {0.f, 0.f, 0.f, 0.f};
        #pragma unroll
        for (int ks = 0; ks < 4; ks++)
            mma16816(lacc, pfrag[ks], ones);
        lA = lA * aA + lacc[0];
        lB = lB * aB + lacc[2];

        #pragma unroll
        for (int nt = 0; nt < 8; nt++) {
            o[nt][0] *= aA; o[nt][1] *= aA;
            o[nt][2] *= aB; o[nt][3] *= aB;
        }

        // ---- O += P V (register-pipelined V fragments) ----
        {
            uint32_t vb[2][4];
            ldm_x4_trans(vb[0], aVh + voff[0]);
            #pragma unroll
            for (int ks = 0; ks < 4; ks++) {
                const uint32_t ro = (uint32_t)(ks * 16 * QSTR) * 4;
                (void)ro;
                #pragma unroll
                for (int np = 0; np < 4; np++) {
                    const int i  = ks * 4 + np;
                    const int bp = i & 1;
                    if (i < 15) {
                        const int ni = i + 1;
                        ldm_x4_trans(vb[bp ^ 1],
                                     aVh + (uint32_t)((ni >> 2) * 16 * QSTR) * 4
                                         + voff[ni & 3]);
                    }
                    mma16816(o[np * 2],     pfrag[ks], &vb[bp][0]);
                    mma16816(o[np * 2 + 1], pfrag[ks], &vb[bp][2]);
                }
            }
        }
        buf++; if (buf == 3) buf = 0;
    }

    // normalize + write yh fp16
    float liA = 1.0f / lA, liB = 1.0f / lB;
    #pragma unroll
    for (int nt = 0; nt < 8; nt++) {
        int col = nt * 8 + 2 * fc;
        size_t gA = headoff + (size_t)rowAg * CDIM + col;
        size_t gB = headoff + (size_t)rowBg * CDIM + col;
        *(uint32_t*)&Yh[gA] = cvt2h(o[nt][0] * liA, o[nt][1] * liA);
        *(uint32_t*)&Yh[gB] = cvt2h(o[nt][2] * liB, o[nt][3] * liB);
    }
}

// ---------------------------------------------------------------------------
// Launch
// ---------------------------------------------------------------------------
extern "C" void kernel_launch(void* const* d_in, const int* in_sizes, int n_in,
                              void* d_out, int out_size)
{
    const float* x  = (const float*)d_in[0];
    const float* Wq = (const float*)d_in[1];
    const float* bq = (const float*)d_in[2];
    const float* Wk = (const float*)d_in[3];
    const float* bk = (const float*)d_in[4];
    const float* Wv = (const float*)d_in[5];
    const float* bv = (const float*)d_in[6];
    const float* Wo = (const float*)d_in[7];
    const float* bo = (const float*)d_in[8];
    float* out = (float*)d_out;

    __half *xh, *qh, *kh, *vh, *yh;
    __half *wqh, *wkh, *wvh, *woh;
    cudaGetSymbolAddress((void**)&xh, g_xh);
    cudaGetSymbolAddress((void**)&qh, g_qh);
    cudaGetSymbolAddress((void**)&kh, g_kh);
    cudaGetSymbolAddress((void**)&vh, g_vh);
    cudaGetSymbolAddress((void**)&yh, g_yh);
    cudaGetSymbolAddress((void**)&wqh, g_wqh);
    cudaGetSymbolAddress((void**)&wkh, g_wkh);
    cudaGetSymbolAddress((void**)&wvh, g_wvh);
    cudaGetSymbolAddress((void**)&woh, g_woh);

    cudaFuncSetAttribute(attn_mma,
                         cudaFuncAttributeMaxDynamicSharedMemorySize, ATTN_SMEM);
    cudaFuncSetAttribute(gemm_qkv,
                         cudaFuncAttributeMaxDynamicSharedMemorySize, GEMM_SMEM);
    cudaFuncSetAttribute(gemm_o,
                         cudaFuncAttributeMaxDynamicSharedMemorySize, GEMM_SMEM);

    const int nw4 = CDIM * CDIM / 4;   // float4 per weight / x-quarter
    const int xq  = CDIM * CDIM;       // elements per x quarter

    // 1) all fp32->fp16 converts in one launch
    CvtAll ca;
    ca.in[0] = Wq; ca.out[0] = wqh;
    ca.in[1] = Wk; ca.out[1] = wkh;
    ca.in[2] = Wv; ca.out[2] = wvh;
    ca.in[3] = Wo; ca.out[3] = woh;
    for (int q = 0; q < 4; q++) {
        ca.in[4 + q]  = x + (size_t)q * xq;
        ca.out[4 + q] = xh + (size_t)q * xq;
    }
    dim3 cgrid(nw4 / 256, 8);
    cvt8_kernel<<<cgrid, 256>>>(ca, nw4);

    // 2) merged Q/K/V projection
    GemmBatch gb;
    gb.Bh[0] = wqh; gb.bias[0] = bq; gb.Ch[0] = qh;
    gb.Bh[1] = wkh; gb.bias[1] = bk; gb.Ch[1] = kh;
    gb.Bh[2] = wvh; gb.bias[2] = bv; gb.Ch[2] = vh;
    dim3 qkvgrid(CDIM / 128, MROWS / 128, 3);   // (8, 32, 3)
    gemm_qkv<<<qkvgrid, 256, GEMM_SMEM>>>(gb, xh);

    // 3) attention
    dim3 agrid(TSEQ / 128, BATCH * NHEAD);  // (16, 32)
    attn_mma<<<agrid, 256, ATTN_SMEM>>>(qh, kh, vh, yh);

    // 4) output projection
    dim3 ogrid(CDIM / 128, MROWS / 128);    // (8, 32)
    gemm_o<<<ogrid, 256, GEMM_SMEM>>>(yh, woh, bo, out);
}